// round 2
// baseline (speedup 1.0000x reference)
#include <cuda_runtime.h>
#include <stdint.h>

#define BB 16
#define AA 12
#define HH 64
#define WW 64
#define GG 64
#define NN (AA*HH*WW)        /* 49152 anchors per batch */
#define TOT (BB*NN)          /* 786432 */
#define NBUCK 8192
#define SENT 0xFFFFFFFFu

// ---------------- scratch (static __device__, no allocation) ----------------
__device__ unsigned g_ubuf[TOT];        // 23-bit mantissa of r for label-0 elems, else SENT
__device__ unsigned g_hist[BB*NBUCK];   // per-row histogram over u>>10
__device__ unsigned g_pos, g_neg;       // global pos/neg counts
__device__ int      g_T[BB];            // per-row boundary bucket (-1 = none disabled)
__device__ unsigned g_S[BB];            // count strictly above boundary bucket
__device__ unsigned g_cutoff;
__device__ int      g_flag;             // neg_cnt > cutoff

// ------- Threefry-2x32-20, key=(0,42), PARTITIONABLE layout -----------------
// Per element i (size < 2^32): counter block (hi,lo) = (0, i).
// 32-bit output = out0 ^ out1 (XOR fold), per _threefry_random_bits_partitionable.
__device__ __forceinline__ unsigned threefry_bits(unsigned i) {
    unsigned x0 = 0u, x1 = i;
    const unsigned k0 = 0u, k1 = 42u, k2 = 0x1BD11BDAu ^ 0u ^ 42u;
    x0 += k0; x1 += k1;
#define TFR(r) { x0 += x1; x1 = __funnelshift_l(x1, x1, (r)); x1 ^= x0; }
    TFR(13) TFR(15) TFR(26) TFR(6)   x0 += k1; x1 += k2 + 1u;
    TFR(17) TFR(29) TFR(16) TFR(24)  x0 += k2; x1 += k0 + 2u;
    TFR(13) TFR(15) TFR(26) TFR(6)   x0 += k0; x1 += k1 + 3u;
    TFR(17) TFR(29) TFR(16) TFR(24)  x0 += k1; x1 += k2 + 4u;
    TFR(13) TFR(15) TFR(26) TFR(6)   x0 += k2; x1 += k0 + 5u;
#undef TFR
    return x0 ^ x1;
}

// ---------------- kernel 0: zero scratch -----------------------------------
__global__ void zero_kernel() {
    int i = blockIdx.x * blockDim.x + threadIdx.x;
    if (i < BB*NBUCK) g_hist[i] = 0u;
    if (i == 0) { g_pos = 0u; g_neg = 0u; }
}

// ---------------- kernel 1: IoU / labels / targets / PRNG / hist -----------
__global__ void __launch_bounds__(256) main_kernel(
        const float* __restrict__ gt,       // (B,G,4)
        const float* __restrict__ anchors,  // (A,H,W,4) flattened = (N,4)
        float* __restrict__ out)            // (B,N,5)
{
    __shared__ float s_gx0[GG], s_gy0[GG], s_gx1[GG], s_gy1[GG], s_ga[GG];
    __shared__ float s_g0[GG*4];           // raw batch-0 gt boxes (targets use these!)

    const int b = blockIdx.y;
    const int t = threadIdx.x;

    if (t < GG) {
        const float* gp = gt + ((size_t)b*GG + t)*4;
        float x0 = gp[0], y0 = gp[1], w = gp[2], h = gp[3];
        s_gx0[t] = x0; s_gy0[t] = y0;
        s_gx1[t] = __fadd_rn(x0, w);
        s_gy1[t] = __fadd_rn(y0, h);
        s_ga[t]  = __fmul_rn(w, h);
    } else if (t < 2*GG) {
        int g = t - GG;
        const float* gp = gt + (size_t)g*4;   // batch 0 (gt_flat[argmax] quirk)
        s_g0[g*4+0] = gp[0]; s_g0[g*4+1] = gp[1];
        s_g0[g*4+2] = gp[2]; s_g0[g*4+3] = gp[3];
    }
    __syncthreads();

    const int n = blockIdx.x * 256 + t;
    const float4 a4 = *(const float4*)(anchors + (size_t)n*4);
    const float ax0 = a4.x, ay0 = a4.y, aw = a4.z, ah = a4.w;

    const float L = 63.0f;
    const bool keep =
        (ax0 >= 0.f) && (ay0 >= 0.f) && (aw >= 0.f) && (ah >= 0.f) &&
        (ax0 <= L) && (ay0 <= L) &&
        (__fsub_rn(__fadd_rn(ax0, aw), 1.0f) <= L) &&
        (__fsub_rn(__fadd_rn(ay0, ah), 1.0f) <= L);

    const float ax1   = __fadd_rn(ax0, aw);
    const float ay1   = __fadd_rn(ay0, ah);
    const float aarea = __fmul_rn(aw, ah);

    float best = -1.0f;
    int   bg   = 0;
#pragma unroll 8
    for (int g = 0; g < GG; ++g) {
        float iw = fmaxf(0.f, __fsub_rn(fminf(ax1, s_gx1[g]), fmaxf(ax0, s_gx0[g])));
        float ih = fmaxf(0.f, __fsub_rn(fminf(ay1, s_gy1[g]), fmaxf(ay0, s_gy0[g])));
        float inter = __fmul_rn(iw, ih);
        float uni   = __fsub_rn(__fadd_rn(aarea, s_ga[g]), inter);
        float ov    = __fdiv_rn(inter, uni);
        if (ov == 0.f) ov = 1e-10f;            // jnp.where(ov==0, 1e-10, ov)
        if (ov > best) { best = ov; bg = g; }  // strict > == first-max argmax
    }

    float label = -1.0f;
    bool pos = false, neg = false, lab0 = false;
    if (keep) {
        if (best >= 0.7f)       label = 1.0f;
        else if (best <= 0.3f) { label = 0.0f; lab0 = true; }
        pos = (best > 0.7f);    // pos_cnt uses strict >
        neg = (best < 0.3f);    // neg_cnt uses strict <
    }

    const size_t i = (size_t)b*NN + n;
    float* op = out + i*5;
    op[0] = label;
    if (keep) {
        op[1] = __fsub_rn(ax0, __fmul_rn(s_g0[bg*4+0], 0.0625f));
        op[2] = __fsub_rn(ay0, __fmul_rn(s_g0[bg*4+1], 0.0625f));
        op[3] = __fsub_rn(aw,  __fmul_rn(s_g0[bg*4+2], 0.0625f));
        op[4] = __fsub_rn(ah,  __fmul_rn(s_g0[bg*4+3], 0.0625f));
    } else {
        op[1] = 0.f; op[2] = 0.f; op[3] = 0.f; op[4] = 0.f;
    }

    unsigned u = SENT;
    if (lab0) {
        unsigned bits = threefry_bits((unsigned)i);
        u = bits >> 9;                                 // 23-bit mantissa; ordering == r ordering
        atomicAdd(&g_hist[b*NBUCK + (u >> 10)], 1u);
    }
    g_ubuf[i] = u;

    unsigned bp = __ballot_sync(0xFFFFFFFFu, pos);
    unsigned bn = __ballot_sync(0xFFFFFFFFu, neg);
    if ((t & 31) == 0) {
        if (bp) atomicAdd(&g_pos, (unsigned)__popc(bp));
        if (bn) atomicAdd(&g_neg, (unsigned)__popc(bn));
    }
}

// ---------------- kernel 2: find per-row boundary bucket --------------------
// One warp per row; scan 8192 buckets in descending-u order in 32-wide chunks.
__global__ void __launch_bounds__(512) scan_kernel() {
    const int warp = threadIdx.x >> 5;
    const int lane = threadIdx.x & 31;
    if (warp >= BB) return;

    const unsigned pos = g_pos, negc = g_neg;
    const int cutoff = max(1, 3 * (int)pos);
    if (threadIdx.x == 0) {
        g_cutoff = (unsigned)cutoff;
        g_flag   = ((int)negc > cutoff) ? 1 : 0;
    }

    const int b = warp;
    unsigned acc = 0;
    int T = -1; unsigned S = 0; bool found = false;
    for (int c = 0; c < NBUCK/32; ++c) {
        int bucket = (NBUCK - 1) - (c*32 + lane);
        unsigned v = g_hist[b*NBUCK + bucket];
        unsigned incl = v;
        #pragma unroll
        for (int o = 1; o < 32; o <<= 1) {
            unsigned tv = __shfl_up_sync(0xFFFFFFFFu, incl, o);
            if (lane >= o) incl += tv;
        }
        unsigned total = __shfl_sync(0xFFFFFFFFu, incl, 31);
        if (acc + total >= (unsigned)cutoff) {
            bool here = (acc + incl >= (unsigned)cutoff) &&
                        (acc + incl - v <  (unsigned)cutoff);
            unsigned bal = __ballot_sync(0xFFFFFFFFu, here);
            int src = __ffs(bal) - 1;
            T = __shfl_sync(0xFFFFFFFFu, bucket, src);
            S = __shfl_sync(0xFFFFFFFFu, acc + incl - v, src);
            found = true;
            break;
        }
        acc += total;
    }
    if (lane == 0) { g_T[b] = found ? T : -1; g_S[b] = S; }
}

// ---------------- kernel 3: apply disable (bulk + boundary fine-rank) ------
__global__ void __launch_bounds__(256) disable_kernel(float* __restrict__ out) {
    if (!g_flag) return;
    const int b = blockIdx.x;
    const int T = g_T[b];

    __shared__ unsigned s_u[1024];
    __shared__ int      s_idx[1024];
    __shared__ int      s_cnt;
    if (threadIdx.x == 0) s_cnt = 0;
    __syncthreads();

    const unsigned* row = g_ubuf + (size_t)b*NN;

    // Bulk pass: buckets strictly below boundary -> rank >= cutoff -> disable.
    for (int j = threadIdx.x; j < NN; j += 256) {
        unsigned u = row[j];
        if (u == SENT) continue;
        int bucket = (int)(u >> 10);
        if (bucket < T) {
            out[((size_t)b*NN + j)*5] = -1.0f;
        } else if (bucket == T) {
            int p = atomicAdd(&s_cnt, 1);
            if (p < 1024) { s_u[p] = u; s_idx[p] = j; }
        }
    }
    __syncthreads();

    const unsigned S      = g_S[b];
    const unsigned cutoff = g_cutoff;
    const int m = min(s_cnt, 1024);

    if (s_cnt <= 1024) {
        // Exact rank within boundary bucket: stable (r desc, index asc).
        for (int a = threadIdx.x; a < m; a += 256) {
            unsigned ua = s_u[a]; int ia = s_idx[a];
            unsigned cnt = S;
            for (int k = 0; k < m; ++k) {
                unsigned ub = s_u[k];
                if (ub > ua || (ub == ua && s_idx[k] < ia)) cnt++;
            }
            if (cnt >= cutoff) out[((size_t)b*NN + ia)*5] = -1.0f;
        }
    } else {
        // Degenerate fallback (practically unreachable): per-element row scan.
        for (int a = threadIdx.x; a < NN; a += 256) {
            unsigned ua = row[a];
            if (ua == SENT || (int)(ua >> 10) != T) continue;
            unsigned cnt = S;
            for (int j = 0; j < NN; ++j) {
                unsigned uj = row[j];
                if (uj != SENT && (int)(uj >> 10) == T &&
                    (uj > ua || (uj == ua && j < a))) cnt++;
            }
            if (cnt >= cutoff) out[((size_t)b*NN + a)*5] = -1.0f;
        }
    }
}

// ---------------- launch ----------------------------------------------------
extern "C" void kernel_launch(void* const* d_in, const int* in_sizes, int n_in,
                              void* d_out, int out_size) {
    // Robust input selection by element count (metadata order: cls, gt, anchors).
    const float* gt      = (const float*)d_in[1];
    const float* anchors = (const float*)d_in[2];
    for (int k = 0; k < n_in; ++k) {
        if (in_sizes[k] == BB*GG*4) gt      = (const float*)d_in[k];
        if (in_sizes[k] == NN*4)    anchors = (const float*)d_in[k];
    }
    float* out = (float*)d_out;

    zero_kernel<<<(BB*NBUCK + 255)/256, 256>>>();
    dim3 grid(NN/256, BB);
    main_kernel<<<grid, 256>>>(gt, anchors, out);
    scan_kernel<<<1, 512>>>();
    disable_kernel<<<BB, 256>>>(out);
}

// round 3
// speedup vs baseline: 2.4851x; 2.4851x over previous
#include <cuda_runtime.h>
#include <stdint.h>

#define BB 16
#define AA 12
#define HH 64
#define WW 64
#define GG 64
#define NN (AA*HH*WW)        /* 49152 anchors per batch */
#define TOT (BB*NN)          /* 786432 */
#define NBUCK 8192
#define SENT 0xFFFFFFFFu
#define CAP  4096            /* boundary-bucket candidate capacity per row */

// ---------------- scratch (static __device__, no allocation) ----------------
__device__ unsigned g_ubuf[TOT];        // 23-bit mantissa of r for label-0 elems, else SENT
__device__ unsigned g_hist[BB*NBUCK];   // per-row histogram over u>>10
__device__ unsigned g_pos, g_neg;       // global pos/neg counts
__device__ int      g_T[BB];            // per-row boundary bucket (-1 = none disabled)
__device__ unsigned g_S[BB];            // count strictly above boundary bucket
__device__ unsigned g_cutoff;
__device__ int      g_flag;             // neg_cnt > cutoff
__device__ unsigned g_bcnt[BB];         // boundary candidates per row
__device__ unsigned g_bu [BB*CAP];      // boundary candidate u values
__device__ int      g_bidx[BB*CAP];     // boundary candidate indices

// ------- Threefry-2x32-20, key=(0,42), PARTITIONABLE layout -----------------
__device__ __forceinline__ unsigned threefry_bits(unsigned i) {
    unsigned x0 = 0u, x1 = i;
    const unsigned k0 = 0u, k1 = 42u, k2 = 0x1BD11BDAu ^ 0u ^ 42u;
    x0 += k0; x1 += k1;
#define TFR(r) { x0 += x1; x1 = __funnelshift_l(x1, x1, (r)); x1 ^= x0; }
    TFR(13) TFR(15) TFR(26) TFR(6)   x0 += k1; x1 += k2 + 1u;
    TFR(17) TFR(29) TFR(16) TFR(24)  x0 += k2; x1 += k0 + 2u;
    TFR(13) TFR(15) TFR(26) TFR(6)   x0 += k0; x1 += k1 + 3u;
    TFR(17) TFR(29) TFR(16) TFR(24)  x0 += k1; x1 += k2 + 4u;
    TFR(13) TFR(15) TFR(26) TFR(6)   x0 += k2; x1 += k0 + 5u;
#undef TFR
    return x0 ^ x1;
}

// ---------------- kernel 0: zero scratch -----------------------------------
__global__ void zero_kernel() {
    int i = blockIdx.x * blockDim.x + threadIdx.x;
    if (i < BB*NBUCK) g_hist[i] = 0u;
    if (i < BB) g_bcnt[i] = 0u;
    if (i == 0) { g_pos = 0u; g_neg = 0u; }
}

// ---------------- kernel 1: IoU / labels / targets / PRNG / hist -----------
// 2 anchors per thread. Division-free inner loop with exact-guard fallback:
// update candidate iff inter >= bslack*uni with bslack = best*(1-2^-22);
// then the exact __fdiv_rn + (ov > best) decides — bit-identical to reference.
__global__ void __launch_bounds__(256) main_kernel(
        const float* __restrict__ gt,       // (B,G,4)
        const float* __restrict__ anchors,  // (N,4)
        float* __restrict__ out)            // (B,N,5)
{
    __shared__ float2 s_g01[GG];   // (gx0, gy0)
    __shared__ float2 s_g11[GG];   // (gx1, gy1)
    __shared__ float  s_ga [GG];   // gt area
    __shared__ float4 s_g0 [GG];   // raw batch-0 gt boxes (targets use these!)

    const int b = blockIdx.y;
    const int t = threadIdx.x;

    if (t < GG) {
        const float4 gp = *(const float4*)(gt + ((size_t)b*GG + t)*4);
        s_g01[t] = make_float2(gp.x, gp.y);
        s_g11[t] = make_float2(__fadd_rn(gp.x, gp.z), __fadd_rn(gp.y, gp.w));
        s_ga[t]  = __fmul_rn(gp.z, gp.w);
    } else if (t < 2*GG) {
        int g = t - GG;
        s_g0[g] = *(const float4*)(gt + (size_t)g*4);   // batch 0 quirk
    }
    __syncthreads();

    const int n0 = (blockIdx.x * 256 + t) * 2;   // two consecutive anchors

    float4 a0 = *(const float4*)(anchors + (size_t)n0*4);
    float4 a1 = *(const float4*)(anchors + (size_t)(n0+1)*4);

    float ax1_0 = __fadd_rn(a0.x, a0.z), ay1_0 = __fadd_rn(a0.y, a0.w);
    float ax1_1 = __fadd_rn(a1.x, a1.z), ay1_1 = __fadd_rn(a1.y, a1.w);
    float aarea0 = __fmul_rn(a0.z, a0.w);
    float aarea1 = __fmul_rn(a1.z, a1.w);

    float best0 = -1.0f, best1 = -1.0f;
    float bsl0 = -1.0f,  bsl1 = -1.0f;     // best*(1-2^-22), init negative => first guard passes
    int   bg0 = 0, bg1 = 0;

#pragma unroll 4
    for (int g = 0; g < GG; ++g) {
        const float2 g01 = s_g01[g];
        const float2 g11 = s_g11[g];
        const float  ga  = s_ga[g];

        // anchor 0
        {
            float iw = fmaxf(0.f, __fsub_rn(fminf(ax1_0, g11.x), fmaxf(a0.x, g01.x)));
            float ih = fmaxf(0.f, __fsub_rn(fminf(ay1_0, g11.y), fmaxf(a0.y, g01.y)));
            float inter = __fmul_rn(iw, ih);
            float uni   = __fsub_rn(__fadd_rn(aarea0, ga), inter);
            if (inter >= __fmul_rn(bsl0, uni)) {          // rare
                float ov = __fdiv_rn(inter, uni);
                if (ov == 0.f) ov = 1e-10f;
                if (ov > best0) {
                    best0 = ov; bg0 = g;
                    bsl0 = __fmul_rn(best0, 0.99999976f); // 1 - 2^-22
                }
            }
        }
        // anchor 1
        {
            float iw = fmaxf(0.f, __fsub_rn(fminf(ax1_1, g11.x), fmaxf(a1.x, g01.x)));
            float ih = fmaxf(0.f, __fsub_rn(fminf(ay1_1, g11.y), fmaxf(a1.y, g01.y)));
            float inter = __fmul_rn(iw, ih);
            float uni   = __fsub_rn(__fadd_rn(aarea1, ga), inter);
            if (inter >= __fmul_rn(bsl1, uni)) {
                float ov = __fdiv_rn(inter, uni);
                if (ov == 0.f) ov = 1e-10f;
                if (ov > best1) {
                    best1 = ov; bg1 = g;
                    bsl1 = __fmul_rn(best1, 0.99999976f);
                }
            }
        }
    }

    const float L = 63.0f;
    bool pos = false, neg = false;
    unsigned lab0mask = 0u;

#pragma unroll
    for (int k = 0; k < 2; ++k) {
        const float4 a  = k ? a1 : a0;
        const float best = k ? best1 : best0;
        const int   bg   = k ? bg1 : bg0;
        const int   n    = n0 + k;
        const float ax1  = k ? ax1_1 : ax1_0;
        const float ay1  = k ? ay1_1 : ay1_0;

        const bool keep =
            (a.x >= 0.f) && (a.y >= 0.f) && (a.z >= 0.f) && (a.w >= 0.f) &&
            (a.x <= L) && (a.y <= L) &&
            (__fsub_rn(ax1, 1.0f) <= L) &&
            (__fsub_rn(ay1, 1.0f) <= L);

        float label = -1.0f;
        bool lab0 = false;
        if (keep) {
            if (best >= 0.7f)       label = 1.0f;
            else if (best <= 0.3f) { label = 0.0f; lab0 = true; }
            pos |= (best > 0.7f);
            neg |= (best < 0.3f);    // per-anchor; accumulate via popc below
        }
        // per-anchor pos/neg must be counted individually, not OR'd:
        // handle by ballot below per k. Store flags in bits.
        if (k == 0) { pos = keep && (best > 0.7f); neg = keep && (best < 0.3f); }
        else {
            // count both anchors: use two ballots (handled after loop via vars)
        }

        const size_t i = (size_t)b*NN + n;
        float* op = out + i*5;
        op[0] = label;
        if (keep) {
            const float4 g0 = s_g0[bg];
            op[1] = __fsub_rn(a.x, __fmul_rn(g0.x, 0.0625f));
            op[2] = __fsub_rn(a.y, __fmul_rn(g0.y, 0.0625f));
            op[3] = __fsub_rn(a.z, __fmul_rn(g0.z, 0.0625f));
            op[4] = __fsub_rn(a.w, __fmul_rn(g0.w, 0.0625f));
        } else {
            op[1] = 0.f; op[2] = 0.f; op[3] = 0.f; op[4] = 0.f;
        }

        unsigned u = SENT;
        if (lab0) {
            unsigned bits = threefry_bits((unsigned)i);
            u = bits >> 9;
            atomicAdd(&g_hist[b*NBUCK + (u >> 10)], 1u);
            lab0mask |= (1u << k);
        }
        g_ubuf[i] = u;
    }

    // exact pos/neg counting for both anchors
    {
        const bool keep0 =
            (a0.x >= 0.f) && (a0.y >= 0.f) && (a0.z >= 0.f) && (a0.w >= 0.f) &&
            (a0.x <= L) && (a0.y <= L) &&
            (__fsub_rn(ax1_0, 1.0f) <= L) && (__fsub_rn(ay1_0, 1.0f) <= L);
        const bool keep1 =
            (a1.x >= 0.f) && (a1.y >= 0.f) && (a1.z >= 0.f) && (a1.w >= 0.f) &&
            (a1.x <= L) && (a1.y <= L) &&
            (__fsub_rn(ax1_1, 1.0f) <= L) && (__fsub_rn(ay1_1, 1.0f) <= L);
        int myp = (keep0 && best0 > 0.7f) + (keep1 && best1 > 0.7f);
        int myn = (keep0 && best0 < 0.3f) + (keep1 && best1 < 0.3f);
        // warp reduce
        for (int o = 16; o > 0; o >>= 1) {
            myp += __shfl_down_sync(0xFFFFFFFFu, myp, o);
            myn += __shfl_down_sync(0xFFFFFFFFu, myn, o);
        }
        if ((t & 31) == 0) {
            if (myp) atomicAdd(&g_pos, (unsigned)myp);
            if (myn) atomicAdd(&g_neg, (unsigned)myn);
        }
    }
}

// ---------------- kernel 2: find per-row boundary bucket --------------------
__global__ void __launch_bounds__(512) scan_kernel() {
    const int warp = threadIdx.x >> 5;
    const int lane = threadIdx.x & 31;
    if (warp >= BB) return;

    const unsigned pos = g_pos, negc = g_neg;
    const int cutoff = max(1, 3 * (int)pos);
    if (threadIdx.x == 0) {
        g_cutoff = (unsigned)cutoff;
        g_flag   = ((int)negc > cutoff) ? 1 : 0;
    }

    const int b = warp;
    unsigned acc = 0;
    int T = -1; unsigned S = 0; bool found = false;
    for (int c = 0; c < NBUCK/32; ++c) {
        int bucket = (NBUCK - 1) - (c*32 + lane);
        unsigned v = g_hist[b*NBUCK + bucket];
        unsigned incl = v;
        #pragma unroll
        for (int o = 1; o < 32; o <<= 1) {
            unsigned tv = __shfl_up_sync(0xFFFFFFFFu, incl, o);
            if (lane >= o) incl += tv;
        }
        unsigned total = __shfl_sync(0xFFFFFFFFu, incl, 31);
        if (acc + total >= (unsigned)cutoff) {
            bool here = (acc + incl >= (unsigned)cutoff) &&
                        (acc + incl - v <  (unsigned)cutoff);
            unsigned bal = __ballot_sync(0xFFFFFFFFu, here);
            int src = __ffs(bal) - 1;
            T = __shfl_sync(0xFFFFFFFFu, bucket, src);
            S = __shfl_sync(0xFFFFFFFFu, acc + incl - v, src);
            found = true;
            break;
        }
        acc += total;
    }
    if (lane == 0) { g_T[b] = found ? T : -1; g_S[b] = S; }
}

// ---------------- kernel 3a: bulk disable + boundary collect (wide grid) ----
#define BULK_BLKX 24           /* 24 * 256 * 8 = 49152 = NN */
__global__ void __launch_bounds__(256) bulk_kernel(float* __restrict__ out) {
    if (!g_flag) return;
    const int b = blockIdx.y;
    const int T = g_T[b];
    if (T < 0) return;

    const unsigned* row = g_ubuf + (size_t)b*NN;
    const int base = (blockIdx.x * 256 + threadIdx.x) * 8;

#pragma unroll
    for (int k = 0; k < 8; ++k) {
        int j = base + k;
        unsigned u = row[j];
        if (u == SENT) continue;
        int bucket = (int)(u >> 10);
        if (bucket < T) {
            out[((size_t)b*NN + j)*5] = -1.0f;
        } else if (bucket == T) {
            unsigned p = atomicAdd(&g_bcnt[b], 1u);
            if (p < CAP) { g_bu[b*CAP + p] = u; g_bidx[b*CAP + p] = j; }
        }
    }
}

// ---------------- kernel 3b: boundary fine-rank -----------------------------
__global__ void __launch_bounds__(256) fine_kernel(float* __restrict__ out) {
    if (!g_flag) return;
    const int b = blockIdx.x;
    if (g_T[b] < 0) return;

    __shared__ unsigned s_u[CAP > 2048 ? 2048 : CAP];
    __shared__ int      s_idx[CAP > 2048 ? 2048 : CAP];

    const unsigned mraw = g_bcnt[b];
    const unsigned S = g_S[b];
    const unsigned cutoff = g_cutoff;

    if (mraw <= 2048 && mraw <= CAP) {
        const int m = (int)mraw;
        for (int a = threadIdx.x; a < m; a += 256) {
            s_u[a] = g_bu[b*CAP + a];
            s_idx[a] = g_bidx[b*CAP + a];
        }
        __syncthreads();
        for (int a = threadIdx.x; a < m; a += 256) {
            unsigned ua = s_u[a]; int ia = s_idx[a];
            unsigned cnt = S;
            for (int k = 0; k < m; ++k) {
                unsigned ub = s_u[k];
                if (ub > ua || (ub == ua && s_idx[k] < ia)) cnt++;
            }
            if (cnt >= cutoff) out[((size_t)b*NN + ia)*5] = -1.0f;
        }
    } else {
        // Degenerate fallback: per-element row scan on the boundary bucket.
        const int T = g_T[b];
        const unsigned* row = g_ubuf + (size_t)b*NN;
        for (int a = threadIdx.x; a < NN; a += 256) {
            unsigned ua = row[a];
            if (ua == SENT || (int)(ua >> 10) != T) continue;
            unsigned cnt = S;
            for (int j = 0; j < NN; ++j) {
                unsigned uj = row[j];
                if (uj != SENT && (int)(uj >> 10) == T &&
                    (uj > ua || (uj == ua && j < a))) cnt++;
            }
            if (cnt >= cutoff) out[((size_t)b*NN + a)*5] = -1.0f;
        }
    }
}

// ---------------- launch ----------------------------------------------------
extern "C" void kernel_launch(void* const* d_in, const int* in_sizes, int n_in,
                              void* d_out, int out_size) {
    const float* gt      = (const float*)d_in[1];
    const float* anchors = (const float*)d_in[2];
    for (int k = 0; k < n_in; ++k) {
        if (in_sizes[k] == BB*GG*4) gt      = (const float*)d_in[k];
        if (in_sizes[k] == NN*4)    anchors = (const float*)d_in[k];
    }
    float* out = (float*)d_out;

    zero_kernel<<<(BB*NBUCK + 255)/256, 256>>>();
    dim3 grid(NN/512, BB);                 // 2 anchors per thread
    main_kernel<<<grid, 256>>>(gt, anchors, out);
    scan_kernel<<<1, 512>>>();
    dim3 bgrid(BULK_BLKX, BB);
    bulk_kernel<<<bgrid, 256>>>(out);
    fine_kernel<<<BB, 256>>>(out);
}